// round 16
// baseline (speedup 1.0000x reference)
#include <cuda_runtime.h>

#define INN   40
#define HID   16384
#define OUTN  22
#define FAN0  8192
#define FAN1  11
#define THRESH 0.3f
#define NBLK  64
#define NTHR  256
#define NWARP (NTHR / 32)
#define NTOT  (NBLK * NTHR)             // 16384 threads == HID
#define ROWF  (NTHR * FAN1)             // floats in a block's w1 slice (2816)
#define V4N   (ROWF / 4)                // 704 float4 per array per block
#define DECAY 0.95122942450071400910f   // float32(exp(-1/20))

// Scratch — __device__ globals (allocation-free rule). g_add_h / g_add_o are
// zero at load and restored to zero every execution (zero-on-consume). Sync
// words are MONOTONIC (never reset). g_sync[0] = arrival counter, g_sync[128]
// = gate/replay word: 512B apart => different L2 slices, so polls don't
// contend with arrival atomics at one LTS.
__device__ float g_add_h[HID];
__device__ float g_add_o[OUTN];
__device__ __align__(128) unsigned g_sync[256];   // [0]: bar ctr, [128]: gate

#define BAR_W (&g_sync[0])
#define GEN_W (&g_sync[128])

__device__ __forceinline__ unsigned ld_acquire_gpu(const unsigned* p) {
    unsigned v;
    asm volatile("ld.acquire.gpu.global.b32 %0, [%1];" : "=r"(v) : "l"(p) : "memory");
    return v;
}
__device__ __forceinline__ void st_release_gpu(unsigned* p, unsigned v) {
    asm volatile("st.release.gpu.global.b32 [%0], %1;" :: "l"(p), "r"(v) : "memory");
}
// Arrival atomic with acq_rel: releases this thread's (and, via the preceding
// bar.sync/__syncwarp, the block's) prior writes; acquires others' on return.
__device__ __forceinline__ unsigned atom_add_acqrel_gpu(unsigned* p, unsigned v) {
    unsigned old;
    asm volatile("atom.add.acq_rel.gpu.global.u32 %0, [%1], %2;"
                 : "=r"(old) : "l"(p), "r"(v) : "memory");
    return old;
}

__global__ __launch_bounds__(NTHR, 1)
void snn_fused(const float* __restrict__ spikes,
               const float* __restrict__ w0,
               const int*   __restrict__ tgt0,
               const float* __restrict__ w1,
               const int*   __restrict__ tgt1,
               const int*   __restrict__ mt_p,
               float*       __restrict__ out)
{
    __shared__ float s_bins[NWARP][24];   // warp-private output bins (22 used)
    __shared__ float s_w1[ROWF];          // staged w1 slice (vec4)
    __shared__ int   s_t1[ROWF];          // staged tgt1 slice

    const int tid = threadIdx.x;
    const int gid = blockIdx.x * NTHR + tid;   // one hidden neuron per thread
    const int wrp = tid >> 5;
    const int lan = tid & 31;
    const int i0  = gid >> 11;                 // first input row of my chunks

    // ── Per-thread spike loads (warp-uniform addresses, 2 lines total).
    float spk[5];
#pragma unroll
    for (int k = 0; k < 5; ++k) spk[k] = __ldg(spikes + (i0 + 8 * k));

    // ── Vectorized speculative prefetch of phase-B operands (critical path).
    const float4* w0v = (const float4*)w0;
    const int4*   t0v = (const int4*)tgt0;
    float4 wv[5];
    int4   tv[5];
#pragma unroll
    for (int k = 0; k < 5; ++k) {
        wv[k] = __ldg(w0v + (gid + NTOT * k));
        tv[k] = __ldg(t0v + (gid + NTOT * k));
    }

    // ── Staging loads for this block's w1/tgt1 slice (contiguous, vec4).
    // Registers until after the grid barrier (R15: STS park before bar.sync
    // puts the staging DRAM tail on the global release path).
    float4 swv[3];
    int4   stv[3];
    {
        const float4* wsrc = (const float4*)w1 + blockIdx.x * V4N;
        const int4*   tsrc = (const int4*)tgt1 + blockIdx.x * V4N;
#pragma unroll
        for (int i = 0; i < 3; ++i) {
            const int idx = tid + i * NTHR;
            if (idx < V4N) { swv[i] = __ldg(wsrc + idx); stv[i] = __ldg(tsrc + idx); }
        }
    }
    const int mt = __ldg(mt_p);
    const unsigned gen = ld_acquire_gpu(GEN_W);   // replay index

    // Warp-private bin zeroing — own row only, no block sync needed.
    if (lan < 24) s_bins[wrp][lan] = 0.0f;

    // fac_long = decay^(mt-1): consumed ONLY by a potential finisher (warp 0).
    // Warps 1-7 never touch it — don't burn their issue slots on the chain.
    float fac_long = 1.0f;
    if (wrp == 0)
        for (int k = 1; k < mt; ++k) fac_long *= DECAY;

    // ── Phase B: input -> hidden scatter (t=0). Register spike predicate
    // (warp-uniform), 4 predicated REDs per chunk, operands in registers.
#pragma unroll
    for (int k = 0; k < 5; ++k) {
        const float s = 2.0f * spk[k];
        if (s != 0.0f) {
            atomicAdd(&g_add_h[tv[k].x], s * wv[k].x);
            atomicAdd(&g_add_h[tv[k].y], s * wv[k].y);
            atomicAdd(&g_add_h[tv[k].z], s * wv[k].z);
            atomicAdd(&g_add_h[tv[k].w], s * wv[k].w);
        }
    }

    // ── Barrier 1: bar.sync orders only the block's REDGs before tid0's
    // acq_rel arrival. Gate exit: lane-0 polls + shfl broadcast.
    __syncthreads();
    if (tid == 0) {
        unsigned old = atom_add_acqrel_gpu(BAR_W, 1u);
        if (old == (2u * gen + 1u) * NBLK - 1u)
            st_release_gpu(GEN_W, gen + 1u);               // open gate
    }
    {
        unsigned g = gen;
        do {
            if (lan == 0) g = ld_acquire_gpu(GEN_W);
            g = __shfl_sync(0xffffffffu, g, 0);
        } while (g == gen);
    }

    // ── Phase C. Reload (true dependency) first; zero-on-consume store right
    // behind it (independent, drains during the park); STS park + cheap block
    // sync overlap the reload latency.
    const float a_raw = g_add_h[gid];             // issued immediately
    g_add_h[gid] = 0.0f;                          // zero-on-consume for replay
    {
        float4* sw = (float4*)s_w1;
        int4*   st = (int4*)s_t1;
#pragma unroll
        for (int i = 0; i < 3; ++i) {
            const int idx = tid + i * NTHR;
            if (idx < V4N) { sw[idx] = swv[i]; st[idx] = stv[i]; }
        }
    }
    const bool out_phase = (mt >= 2);             // precompute tail selects
    const bool pot_phase = (mt >= 1);
    __syncthreads();                              // staged slices visible

    float a = a_raw * DECAY;                      // pot_h at end of t=0
    const bool  sp  = (a >= THRESH);
    const float pot = sp ? 0.0f : a;

    // Speculative pot_h store: assume all_f=true => S=2 => fac=DECAY.
    out[2 * OUTN + gid] = pot_phase ? pot * DECAY : 0.0f;

    if (sp) {
        const int base = tid * FAN1;
#pragma unroll
        for (int q = 0; q < FAN1; ++q)
            atomicAdd(&s_bins[wrp][s_t1[base + q]], s_w1[base + q]);
    }
    __syncthreads();                               // all warps' bins + pot_h stores
    if (wrp != 0) return;                          // warps 1..7 done

    // ── Warp 0: post output partials; acq_rel arrival (after __syncwarp)
    // releases the block's adds + pot_h stores. Only the LAST block finalizes.
    float v = 0.0f;
    if (lan < OUTN) {
#pragma unroll
        for (int w = 0; w < NWARP; ++w) v += s_bins[w][lan];
        if (v != 0.0f) atomicAdd(&g_add_o[lan], v);
    }
    __syncwarp();                                  // order lanes' REDGs pre-arrival
    unsigned old = 0;
    if (lan == 0) old = atom_add_acqrel_gpu(BAR_W, 1u);
    const bool fin = __shfl_sync(0xffffffffu, old, 0) == (2u * gen + 2u) * NBLK - 1u;
    if (!fin) return;                              // 63 blocks exit here

    // ── Finisher (warp 0 of last block): acquire came from its arrival.
    float ao = 0.0f;
    if (lan < OUTN) {
        ao = g_add_o[lan];
        g_add_o[lan] = 0.0f;                       // zero-on-consume for replay
    }
    const bool f    = (lan < OUTN) && out_phase && (ao * DECAY >= THRESH);
    const unsigned m = __ballot_sync(0xffffffffu, f | (lan >= OUTN));
    const bool all_f = out_phase && (m == 0xffffffffu);
    const float fac  = all_f ? DECAY : fac_long;   // decay^(S-1)

    if (lan < OUTN) {
        out[lan]        = f ? 1.0f : -1.0f;                   // out_t
        out[OUTN + lan] = out_phase ? ao * fac : 0.0f;        // pot_o
    }

    // Repair (not taken when all outputs fire at t=1): rescale speculative
    // pot_h from pot*DECAY to pot*fac_long. All blocks' pot_h stores are
    // visible via the acq_rel arrival chain.
    if (pot_phase && !all_f) {
        const float r = fac_long / DECAY;
        for (int i = lan; i < HID; i += 32)
            out[2 * OUTN + i] *= r;
    }
}

extern "C" void kernel_launch(void* const* d_in, const int* in_sizes, int n_in,
                              void* d_out, int out_size) {
    const float* spikes = (const float*)d_in[0];   // (40,)
    const float* w0     = (const float*)d_in[1];   // (40, 8192)
    const int*   tgt0   = (const int*)  d_in[2];   // (40, 8192)
    const float* w1     = (const float*)d_in[3];   // (16384, 11)
    const int*   tgt1   = (const int*)  d_in[4];   // (16384, 11)
    const int*   mt     = (const int*)  d_in[5];   // scalar max_timesteps
    float* out = (float*)d_out;

    snn_fused<<<NBLK, NTHR>>>(spikes, w0, tgt0, w1, tgt1, mt, out);
}

// round 17
// speedup vs baseline: 1.0499x; 1.0499x over previous
#include <cuda_runtime.h>

#define INN   40
#define HID   16384
#define OUTN  22
#define FAN0  8192
#define FAN1  11
#define THRESH 0.3f
#define NBLK  64
#define NTHR  256
#define NWARP (NTHR / 32)
#define NTOT  (NBLK * NTHR)             // 16384 threads == HID
#define ROWF  (NTHR * FAN1)             // floats in a block's w1 slice (2816)
#define V4N   (ROWF / 4)                // 704 float4 per array per block
#define DECAY 0.95122942450071400910f   // float32(exp(-1/20))

// Scratch — __device__ globals (allocation-free rule). g_add_h / g_add_o are
// zero at load and restored to zero every execution (zero-on-consume). Sync
// words are MONOTONIC (never reset). g_sync[0] = arrival counter, g_sync[128]
// = gate/replay word: 512B apart => different L2 slices, so polls don't
// contend with arrival atomics at one LTS.
__device__ float g_add_h[HID];
__device__ float g_add_o[OUTN];
__device__ __align__(128) unsigned g_sync[256];   // [0]: bar ctr, [128]: gate

#define BAR_W (&g_sync[0])
#define GEN_W (&g_sync[128])

__device__ __forceinline__ unsigned ld_acquire_gpu(const unsigned* p) {
    unsigned v;
    asm volatile("ld.acquire.gpu.global.b32 %0, [%1];" : "=r"(v) : "l"(p) : "memory");
    return v;
}
__device__ __forceinline__ void st_release_gpu(unsigned* p, unsigned v) {
    asm volatile("st.release.gpu.global.b32 [%0], %1;" :: "l"(p), "r"(v) : "memory");
}
// Arrival atomic with acq_rel: releases this thread's (and, via the preceding
// bar.sync/__syncwarp, the block's) prior writes; acquires others' on return.
__device__ __forceinline__ unsigned atom_add_acqrel_gpu(unsigned* p, unsigned v) {
    unsigned old;
    asm volatile("atom.add.acq_rel.gpu.global.u32 %0, [%1], %2;"
                 : "=r"(old) : "l"(p), "r"(v) : "memory");
    return old;
}

__global__ __launch_bounds__(NTHR, 1)
void snn_fused(const float* __restrict__ spikes,
               const float* __restrict__ w0,
               const int*   __restrict__ tgt0,
               const float* __restrict__ w1,
               const int*   __restrict__ tgt1,
               const int*   __restrict__ mt_p,
               float*       __restrict__ out)
{
    __shared__ float s_bins[NWARP][24];   // warp-private output bins (22 used)
    __shared__ float s_w1[ROWF];          // staged w1 slice (vec4)
    __shared__ int   s_t1[ROWF];          // staged tgt1 slice

    const int tid = threadIdx.x;
    const int gid = blockIdx.x * NTHR + tid;   // one hidden neuron per thread
    const int wrp = tid >> 5;
    const int lan = tid & 31;
    const int i0  = gid >> 11;                 // first input row of my chunks

    // ── Per-thread spike loads (warp-uniform addresses, 2 lines total).
    float spk[5];
#pragma unroll
    for (int k = 0; k < 5; ++k) spk[k] = __ldg(spikes + (i0 + 8 * k));

    // ── Vectorized speculative prefetch of phase-B operands (critical path).
    const float4* w0v = (const float4*)w0;
    const int4*   t0v = (const int4*)tgt0;
    float4 wv[5];
    int4   tv[5];
#pragma unroll
    for (int k = 0; k < 5; ++k) {
        wv[k] = __ldg(w0v + (gid + NTOT * k));
        tv[k] = __ldg(t0v + (gid + NTOT * k));
    }

    // ── Staging loads for this block's w1/tgt1 slice (contiguous, vec4).
    // Kept in REGISTERS until after the grid barrier: the STS park must not
    // sit before bar1's bar.sync, or every block's arrival stalls on these
    // DRAM loads and the global release inherits the slowest block's tail.
    float4 swv[3];
    int4   stv[3];
    {
        const float4* wsrc = (const float4*)w1 + blockIdx.x * V4N;
        const int4*   tsrc = (const int4*)tgt1 + blockIdx.x * V4N;
#pragma unroll
        for (int i = 0; i < 3; ++i) {
            const int idx = tid + i * NTHR;
            if (idx < V4N) { swv[i] = __ldg(wsrc + idx); stv[i] = __ldg(tsrc + idx); }
        }
    }
    const int mt = __ldg(mt_p);
    const unsigned gen = ld_acquire_gpu(GEN_W);   // replay index

    // Warp-private bin zeroing — own row only, no block sync needed.
    if (lan < 24) s_bins[wrp][lan] = 0.0f;

    // fac_long = decay^(mt-1) (hidden under phase B; finisher/repair only)
    float fac_long = 1.0f;
    for (int k = 1; k < mt; ++k) fac_long *= DECAY;

    // ── Phase B: input -> hidden scatter (t=0). Register spike predicate
    // (warp-uniform), 4 predicated REDs per chunk, operands in registers.
#pragma unroll
    for (int k = 0; k < 5; ++k) {
        const float s = 2.0f * spk[k];
        if (s != 0.0f) {
            atomicAdd(&g_add_h[tv[k].x], s * wv[k].x);
            atomicAdd(&g_add_h[tv[k].y], s * wv[k].y);
            atomicAdd(&g_add_h[tv[k].z], s * wv[k].z);
            atomicAdd(&g_add_h[tv[k].w], s * wv[k].w);
        }
    }

    // ── Barrier 1: bar.sync orders ONLY the block's REDGs before tid0's
    // acq_rel arrival (no staging STS in front of it). Gate exit:
    // lane-0 polls + shfl broadcast.
    __syncthreads();
    if (tid == 0) {
        unsigned old = atom_add_acqrel_gpu(BAR_W, 1u);
        if (old == (2u * gen + 1u) * NBLK - 1u)
            st_release_gpu(GEN_W, gen + 1u);               // open gate
    }
    {
        unsigned g = gen;
        do {
            if (lan == 0) g = ld_acquire_gpu(GEN_W);
            g = __shfl_sync(0xffffffffu, g, 0);
        } while (g == gen);
    }

    // ── Phase C. Issue the true-dependency reload first (L2 hit ~250 cyc),
    // park the staged slices while it's in flight, then a cheap block-local
    // sync (STS->LDS visibility) that overlaps the reload latency.
    const float a_raw = g_add_h[gid];             // issued immediately
    {
        float4* sw = (float4*)s_w1;
        int4*   st = (int4*)s_t1;
#pragma unroll
        for (int i = 0; i < 3; ++i) {
            const int idx = tid + i * NTHR;
            if (idx < V4N) { sw[idx] = swv[i]; st[idx] = stv[i]; }
        }
    }
    __syncthreads();                              // staged slices visible
    g_add_h[gid] = 0.0f;                          // zero-on-consume for replay

    float a = a_raw * DECAY;                      // pot_h at end of t=0
    const bool  sp  = (a >= THRESH);
    const float pot = sp ? 0.0f : a;

    // Speculative pot_h store: assume all_f=true => S=2 => fac=DECAY.
    out[2 * OUTN + gid] = (mt >= 1) ? pot * DECAY : 0.0f;

    if (sp) {
        const int base = tid * FAN1;
#pragma unroll
        for (int q = 0; q < FAN1; ++q)
            atomicAdd(&s_bins[wrp][s_t1[base + q]], s_w1[base + q]);
    }
    __syncthreads();                               // all warps' bins + pot_h stores
    if (wrp != 0) return;                          // warps 1..7 done

    // ── Warp 0: post output partials; acq_rel arrival (after __syncwarp)
    // releases the block's adds + pot_h stores. Only the LAST block finalizes.
    float v = 0.0f;
    if (lan < OUTN) {
#pragma unroll
        for (int w = 0; w < NWARP; ++w) v += s_bins[w][lan];
        if (v != 0.0f) atomicAdd(&g_add_o[lan], v);
    }
    __syncwarp();                                  // order lanes' REDGs pre-arrival
    unsigned old = 0;
    if (lan == 0) old = atom_add_acqrel_gpu(BAR_W, 1u);
    const bool fin = __shfl_sync(0xffffffffu, old, 0) == (2u * gen + 2u) * NBLK - 1u;
    if (!fin) return;                              // 63 blocks exit here

    // ── Finisher (warp 0 of last block): acquire came from its arrival.
    float ao = 0.0f;
    if (lan < OUTN) {
        ao = g_add_o[lan];
        g_add_o[lan] = 0.0f;                       // zero-on-consume for replay
    }
    const bool out_phase = (mt >= 2);              // outputs fire at t=1 or never
    const bool f    = (lan < OUTN) && out_phase && (ao * DECAY >= THRESH);
    const unsigned m = __ballot_sync(0xffffffffu, f | (lan >= OUTN));
    const bool all_f = out_phase && (m == 0xffffffffu);
    const float fac  = all_f ? DECAY : fac_long;   // decay^(S-1)

    if (lan < OUTN) {
        out[lan]        = f ? 1.0f : -1.0f;                   // out_t
        out[OUTN + lan] = out_phase ? ao * fac : 0.0f;        // pot_o
    }

    // Repair (not taken when all outputs fire at t=1): rescale speculative
    // pot_h from pot*DECAY to pot*fac_long. All blocks' pot_h stores are
    // visible via the acq_rel arrival chain.
    if (mt >= 1 && !all_f) {
        const float r = fac_long / DECAY;
        for (int i = lan; i < HID; i += 32)
            out[2 * OUTN + i] *= r;
    }
}

extern "C" void kernel_launch(void* const* d_in, const int* in_sizes, int n_in,
                              void* d_out, int out_size) {
    const float* spikes = (const float*)d_in[0];   // (40,)
    const float* w0     = (const float*)d_in[1];   // (40, 8192)
    const int*   tgt0   = (const int*)  d_in[2];   // (40, 8192)
    const float* w1     = (const float*)d_in[3];   // (16384, 11)
    const int*   tgt1   = (const int*)  d_in[4];   // (16384, 11)
    const int*   mt     = (const int*)  d_in[5];   // scalar max_timesteps
    float* out = (float*)d_out;

    snn_fused<<<NBLK, NTHR>>>(spikes, w0, tgt0, w1, tgt1, mt, out);
}